// round 9
// baseline (speedup 1.0000x reference)
#include <cuda_runtime.h>
#include <math.h>

#define SPB       64
#define T_LEN     34
#define NTAB      340
#define BTHREADS  128           // 4 warps = 2 teams x 2 roles
#define JSTRIDE   35

__constant__ int c_flat[T_LEN] = {
    0,1,2,3,4,5,6,7,8,9, 11,
    0,1,2,3,4,5,6,7,8,9, 12,
    0,1,2,3,4,5,6,7,8,9, 10, 13
};

__device__ __forceinline__ float ex2f(float x) {
    float y;
    asm("ex2.approx.ftz.f32 %0, %1;" : "=f"(y) : "f"(x));
    return y;
}
__device__ __forceinline__ float rcpf(float x) {
    float y;
    asm("rcp.approx.ftz.f32 %0, %1;" : "=f"(y) : "f"(x));
    return y;
}
// gelu via A&S 7.1.26 erf (|err|<=1.5e-7)
__device__ __forceinline__ float gelu_fast(float z) {
    float a  = z * 0.70710678118654752f;
    float ax = fabsf(a);
    float t  = rcpf(fmaf(0.3275911f, ax, 1.0f));
    float p  = t * fmaf(t, fmaf(t, fmaf(t, fmaf(t, 1.061405429f, -1.453152027f),
                                        1.421413741f), -0.284496736f), 0.254829592f);
    float em = ex2f(-1.4426950408889634f * a * a);
    float er = fmaf(-p, em, 1.0f);
    er = copysignf(er, a);
    return 0.5f * z * (1.0f + er);
}

// Factorized attention segment: queries t = Q0..Q0+NQ-1.
// d(t,s) = rt * rs * G[t][s]; G rows pre-gathered per segment: sG[GBASE + s*12 + i].
template<int Q0, int NQ, int GBASE>
__device__ __forceinline__ void attn_seg_f(
    const unsigned short* __restrict__ jrow,   // byte offsets (tok*8) into tab2
    const char* __restrict__ tb,               // (const char*)tab2
    const float* __restrict__ sG,
    float2* __restrict__ urow)
{
    float rt[NQ], dn[NQ], bb[NQ];
    #pragma unroll
    for (int i = 0; i < NQ; ++i) {
        rt[i] = *(const float*)(tb + (int)jrow[Q0 + i]);
        dn[i] = 0.f; bb[i] = 0.f;
    }
    #pragma unroll 2
    for (int s = 0; s <= Q0; ++s) {
        const float2 kv = *(const float2*)(tb + (int)jrow[s]);
        const float* g = sG + GBASE + s * 12;
        float gv[NQ];
        {
            float4 ga = *(const float4*)g;
            gv[0]=ga.x; gv[1]=ga.y; gv[2]=ga.z; gv[3]=ga.w;
            if (NQ > 4) {
                float4 gb = *(const float4*)(g + 4);
                gv[4]=gb.x; if (NQ>5) gv[5]=gb.y; if (NQ>6) gv[6]=gb.z; if (NQ>7) gv[7]=gb.w;
            }
            if (NQ > 8) gv[8] = g[8];
        }
        #pragma unroll
        for (int i = 0; i < NQ; ++i) {
            float d = (rt[i] * gv[i]) * kv.x;
            float e = ex2f(d);
            dn[i] += e;
            bb[i]  = fmaf(e, kv.y, bb[i]);
        }
    }
    urow[Q0] = make_float2(dn[0], bb[0]);
    #pragma unroll
    for (int seg = 1; seg < NQ; ++seg) {
        const int s = Q0 + seg;
        const float2 kv = *(const float2*)(tb + (int)jrow[s]);
        const float* g = sG + GBASE + s * 12;
        float gv[NQ];
        {
            float4 ga = *(const float4*)g;
            gv[0]=ga.x; gv[1]=ga.y; gv[2]=ga.z; gv[3]=ga.w;
            if (NQ > 4) {
                float4 gb = *(const float4*)(g + 4);
                gv[4]=gb.x; if (NQ>5) gv[5]=gb.y; if (NQ>6) gv[6]=gb.z; if (NQ>7) gv[7]=gb.w;
            }
            if (NQ > 8) gv[8] = g[8];
        }
        #pragma unroll
        for (int i = seg; i < NQ; ++i) {
            float d = (rt[i] * gv[i]) * kv.x;
            float e = ex2f(d);
            dn[i] += e;
            bb[i]  = fmaf(e, kv.y, bb[i]);
        }
        urow[s] = make_float2(dn[seg], bb[seg]);
    }
}

__global__ __launch_bounds__(BTHREADS, 7)
void micro_fused9(
    const int*   __restrict__ idx,
    const float* __restrict__ tokA,
    const float* __restrict__ tokStart,
    const float* __restrict__ tokStride,
    const float* __restrict__ z_hi,
    const float* __restrict__ specialEq,
    const float* __restrict__ qW,         // (4,3)
    const float* __restrict__ phase,
    const float* __restrict__ outA,       // (5,)
    const float* __restrict__ outB,       // (5,)
    const float* __restrict__ nw,         // (5,)
    const float* __restrict__ fc1,        // (2,5)
    const float* __restrict__ hp,         // (2,5)
    float*       __restrict__ out,        // (B,34,10)
    int B)
{
    __shared__ float  s_G  [1032];               // 4 segments: bases 0,108,312,624, stride 12
    __shared__ float2 s_t2 [NTAB];               // (r, r*Vt(c)) per (tpos,digit)
    __shared__ float4 s_xc [10];                 // (x0, x1, Vt, x0^2+x1^2) per digit
    __shared__ float4 s_xp [T_LEN];              // (p0, p1, p2, |p|^2) per position
    __shared__ unsigned short s_j[SPB * JSTRIDE];// byte offset (tok*8)
    __shared__ unsigned char  s_c[SPB * JSTRIDE];// digit
    __shared__ float2 s_u  [SPB * T_LEN + 2];    // (den,b) -> (u0,u1); also overlays s_mt/s_pt in build
    __shared__ float  s_cB[5], s_hp[10], s_wf[10], s_wh[10];

    const int  tid       = threadIdx.x;
    const long base_tok  = (long)blockIdx.x * (SPB * T_LEN);
    const long total_tok = (long)B * T_LEN;

    // build-time overlays on s_u (dead until after attention)
    float4* s_mt = reinterpret_cast<float4*>(s_u);          // [34] Mtilde
    float4* s_pt = reinterpret_cast<float4*>(s_u) + T_LEN;  // [34] ptilde

    // ---- phase 1: idx load + small tables ----
    #pragma unroll
    for (int r = 0; r < 17; ++r) {
        int li = tid + r * BTHREADS;                // 0..2175
        int  yy = li / T_LEN;
        int  ss = li - yy * T_LEN;
        long g  = base_tok + li;
        int  v  = (g < total_tok) ? idx[g] : 0;
        s_j[yy * JSTRIDE + ss] = (unsigned short)((ss * 10 + v) << 3);
        s_c[yy * JSTRIDE + ss] = (unsigned char)v;
    }
    if (tid < 5)  s_cB[tid] = outB[tid];
    if (tid < 10) {
        s_hp[tid] = hp[tid];
        int cc = tid % 5;
        s_wf[tid] = nw[cc] * fc1[tid];
        s_wh[tid] = nw[cc] * hp[tid];
    }
    if (tid < T_LEN) {                      // position tables + Mtilde
        const int f = c_flat[tid];
        float p0, p1, p2;
        if (f < 10) {
            float a = 0.6283185307179586f * (float)f;
            p0 = 3.5f * __cosf(a);
            p1 = 3.5f * __sinf(a);
            p2 = 0.15f * (float)f;
        } else if (f == 10) {
            p0 = z_hi[0]; p1 = z_hi[1]; p2 = z_hi[2];
        } else if (f == 12) {
            p0 = specialEq[0]; p1 = specialEq[1]; p2 = specialEq[2];
        } else {
            p0 = p1 = p2 = 0.0f;
        }
        s_xp[tid] = make_float4(p0, p1, p2, p0*p0 + p1*p1 + p2*p2);

        float pt0 = p0 * nw[2], pt1 = p1 * nw[3], pt2 = p2 * nw[4];
        s_pt[tid] = make_float4(pt0, pt1, pt2, 0.f);

        float q0 = qW[0]*pt0 + qW[1]*pt1 + qW[2]*pt2;
        float q1 = qW[3]*pt0 + qW[4]*pt1 + qW[5]*pt2;
        float q2 = qW[6]*pt0 + qW[7]*pt1 + qW[8]*pt2;
        float q3 = qW[9]*pt0 + qW[10]*pt1 + qW[11]*pt2;
        float cp = __cosf(phase[0]);
        float sp = __sinf(phase[0]);
        float r0  = q0*cp - q1*sp;
        float r1v = q0*sp + q1*cp;
        float r2v = q2*cp - q3*sp;
        float r3  = q2*sp + q3*cp;
        const float LG = 0.5f * 1.4426950408889634f;
        s_mt[tid] = make_float4(
            LG*(r0*qW[0] + r1v*qW[3] + r2v*qW[6] + r3*qW[9]),
            LG*(r0*qW[1] + r1v*qW[4] + r2v*qW[7] + r3*qW[10]),
            LG*(r0*qW[2] + r1v*qW[5] + r2v*qW[8] + r3*qW[11]), 0.f);
    }
    if (tid >= 64 && tid < 74) {            // digit table (separate warps from pos build)
        const int c = tid - 64;
        float ang = tokStart[0] + (float)c * tokStride[0];
        float amp = tokA[0];
        float x0 = amp * __cosf(ang);
        float x1 = amp * __sinf(ang);
        float w0s = hp[0]*outA[0] + hp[1]*outA[1] + hp[2]*outA[2] + hp[3]*outA[3] + hp[4]*outA[4];
        float w1s = hp[5]*outA[0] + hp[6]*outA[1] + hp[7]*outA[2] + hp[8]*outA[3] + hp[9]*outA[4];
        float vt  = x0 * nw[0] * w0s + x1 * nw[1] * w1s;
        s_xc[c] = make_float4(x0, x1, vt, x0*x0 + x1*x1);
    }
    __syncthreads();

    // ---- phase 2: tab2 (340) + G segment arrays ----
    #pragma unroll
    for (int r = 0; r < 3; ++r) {
        int i = tid + r * BTHREADS;
        if (i < NTAB) {
            int tp = i / 10;
            int c  = i - tp * 10;
            float rr = rsqrtf(fmaf(0.2f, s_xc[c].w + s_xp[tp].w, 1e-5f));
            s_t2[i] = make_float2(rr, rr * s_xc[c].z);
        }
    }
    // segments: (base, q0, NQ, rows)
    {
        // seg0: base 0,   q0 0,  NQ 9, rows 9   -> 81 items
        for (int e = tid; e < 9 * 9; e += BTHREADS) {
            int s = e / 9, i = e - s * 9;
            float4 m = s_mt[0 + i], p = s_pt[s];
            s_G[0 + s * 12 + i] = fmaf(m.x, p.x, fmaf(m.y, p.y, m.z * p.z));
        }
        // seg1: base 108, q0 9,  NQ 8, rows 17  -> 136
        for (int e = tid; e < 17 * 8; e += BTHREADS) {
            int s = e / 8, i = e - s * 8;
            float4 m = s_mt[9 + i], p = s_pt[s];
            s_G[108 + s * 12 + i] = fmaf(m.x, p.x, fmaf(m.y, p.y, m.z * p.z));
        }
        // seg2: base 312, q0 17, NQ 9, rows 26  -> 234
        for (int e = tid; e < 26 * 9; e += BTHREADS) {
            int s = e / 9, i = e - s * 9;
            float4 m = s_mt[17 + i], p = s_pt[s];
            s_G[312 + s * 12 + i] = fmaf(m.x, p.x, fmaf(m.y, p.y, m.z * p.z));
        }
        // seg3: base 624, q0 26, NQ 8, rows 34  -> 272
        for (int e = tid; e < 34 * 8; e += BTHREADS) {
            int s = e / 8, i = e - s * 8;
            float4 m = s_mt[26 + i], p = s_pt[s];
            s_G[624 + s * 12 + i] = fmaf(m.x, p.x, fmaf(m.y, p.y, m.z * p.z));
        }
    }
    __syncthreads();

    // ---- phase 3: attention (writes raw (den,b) to s_u; overlays now dead) ----
    {
        const int lane = tid & 31;
        const int warp = tid >> 5;
        const int team = warp >> 1;
        const int role = warp & 1;
        const int y    = lane + (team << 5);
        const unsigned short* __restrict__ jrow = s_j + y * JSTRIDE;
        const char* __restrict__ tb = (const char*)s_t2;
        float2* __restrict__ urow = s_u + y * T_LEN;

        if (role == 0) {
            attn_seg_f<0, 9, 0>  (jrow, tb, s_G, urow);   // 9 steps
            attn_seg_f<26,8, 624>(jrow, tb, s_G, urow);   // 34 steps
        } else {
            attn_seg_f<9, 8, 108>(jrow, tb, s_G, urow);   // 17 steps
            attn_seg_f<17,9, 312>(jrow, tb, s_G, urow);   // 26 steps
        }
    }
    __syncthreads();

    // ---- phase 4: epilogue, in-place s_u: (den,b) -> (u0,u1) ----
    #pragma unroll
    for (int r = 0; r < 17; ++r) {
        int it = tid + r * BTHREADS;                // 0..2175
        const int y = it / T_LEN;
        const int t = it - y * T_LEN;
        const float2 db = s_u[it];
        const float dA = __fdividef(db.y, db.x);
        const int c = (int)s_c[y * JSTRIDE + t];

        const float4 xc = s_xc[c];                  // x0,x1
        const float4 xp = s_xp[t];                  // p0,p1,p2
        float X0 = fmaf(dA, s_cB[0], xc.x);
        float X1 = fmaf(dA, s_cB[1], xc.y);
        float X2 = fmaf(dA, s_cB[2], xp.x);
        float X3 = fmaf(dA, s_cB[3], xp.y);
        float X4 = fmaf(dA, s_cB[4], xp.z);

        float ss1 = fmaf(X0,X0, fmaf(X1,X1, fmaf(X2,X2, fmaf(X3,X3, X4*X4))));
        float r1  = rsqrtf(fmaf(0.2f, ss1, 1e-5f));
        float z0 = r1 * (X0*s_wf[0] + X1*s_wf[1] + X2*s_wf[2] + X3*s_wf[3] + X4*s_wf[4]);
        float z1 = r1 * (X0*s_wf[5] + X1*s_wf[6] + X2*s_wf[7] + X3*s_wf[8] + X4*s_wf[9]);
        float g0 = gelu_fast(z0);
        float g1 = gelu_fast(z1);
        float Y0 = X0 + g0*s_hp[0] + g1*s_hp[5];
        float Y1 = X1 + g0*s_hp[1] + g1*s_hp[6];
        float Y2 = X2 + g0*s_hp[2] + g1*s_hp[7];
        float Y3 = X3 + g0*s_hp[3] + g1*s_hp[8];
        float Y4 = X4 + g0*s_hp[4] + g1*s_hp[9];

        float ss2 = fmaf(Y0,Y0, fmaf(Y1,Y1, fmaf(Y2,Y2, fmaf(Y3,Y3, Y4*Y4))));
        float r2  = rsqrtf(fmaf(0.2f, ss2, 1e-5f));
        float u0 = r2 * (Y0*s_wh[0] + Y1*s_wh[1] + Y2*s_wh[2] + Y3*s_wh[3] + Y4*s_wh[4]);
        float u1 = r2 * (Y0*s_wh[5] + Y1*s_wh[6] + Y2*s_wh[7] + Y3*s_wh[8] + Y4*s_wh[9]);

        s_u[it] = make_float2(u0, u1);
    }
    __syncthreads();

    // ---- phase 5: coalesced float4 output ----
    const long base_f  = base_tok * 10;
    const long total_f = total_tok * 10;
    float* __restrict__ ob = out + base_f;
    const int nf4 = (SPB * T_LEN * 10) / 4;         // 5440

    for (int f4 = tid; f4 < nf4; f4 += BTHREADS) {
        const int el = f4 * 4;
        if (base_f + el + 4 <= total_f) {
            int tq = el / 10;
            int d  = el - tq * 10;
            float2 u = s_u[tq];
            float vv[4];
            #pragma unroll
            for (int k2 = 0; k2 < 4; ++k2) {
                float4 xc = s_xc[d];
                vv[k2] = fmaf(u.y, xc.y, u.x * xc.x);
                if (++d == 10) { d = 0; ++tq; u = s_u[tq]; }
            }
            reinterpret_cast<float4*>(ob)[f4] = make_float4(vv[0], vv[1], vv[2], vv[3]);
        }
    }
}

extern "C" void kernel_launch(void* const* d_in, const int* in_sizes, int n_in,
                              void* d_out, int out_size)
{
    const int B = in_sizes[0] / T_LEN;
    const int grid = (B + SPB - 1) / SPB;
    micro_fused9<<<grid, BTHREADS>>>(
        (const int*)d_in[0],
        (const float*)d_in[1],
        (const float*)d_in[2],
        (const float*)d_in[3],
        (const float*)d_in[4],
        (const float*)d_in[5],
        (const float*)d_in[6],
        (const float*)d_in[7],
        (const float*)d_in[8],
        (const float*)d_in[9],
        (const float*)d_in[10],
        (const float*)d_in[11],
        (const float*)d_in[12],
        (float*)d_out, B);
}